// round 12
// baseline (speedup 1.0000x reference)
#include <cuda_runtime.h>
#include <cuda_fp16.h>
#include <cstdint>

// out[64,8192] = x[64,8192] @ blockdiag(blocks), 32 diagonal 256x256 blocks.
// Grid 128 = 32 blocks x 4 col-chunks of 64. Per CTA:
//   out[0:64, col0:col0+64] = x[0:64, k0:k0+256] @ B[k0:k0+256, col0:col0+64]
//
// Single-term fp16 HMMA (rel_err ~3e-4). 1024 threads = 32 warps.
// R12: intra-CTA K-split. Warps 0-15 -> k[0,128), warps 16-31 -> k[128,256),
// each half = 4m x 4n grid of 16x16 warp tiles (B via ldmatrix.x4.trans).
// LDSM traffic/CTA 384KB -> 256KB (the dominant L1tex wavefront source).
// Halves reduced via 16KB smem at the end. STS merged to uint4.

#define NROW 8192

#define OFF_AH 0          // 32KB: 64 rows x 512B fp16, swizzled
#define OFF_BH 32768      // 32KB: 256 rows x 128B fp16, swizzled
#define SMEM_BYTES 65536

__device__ __forceinline__ uint32_t smem_u32(const void* p) {
    uint32_t a;
    asm("{ .reg .u64 t; cvta.to.shared.u64 t, %1; cvt.u32.u64 %0, t; }" : "=r"(a) : "l"(p));
    return a;
}
__device__ __forceinline__ void ldsm_x4(uint32_t* r, uint32_t addr) {
    asm volatile("ldmatrix.sync.aligned.m8n8.x4.shared.b16 {%0,%1,%2,%3}, [%4];"
                 : "=r"(r[0]), "=r"(r[1]), "=r"(r[2]), "=r"(r[3]) : "r"(addr));
}
__device__ __forceinline__ void ldsm_x4_t(uint32_t* r, uint32_t addr) {
    asm volatile("ldmatrix.sync.aligned.m8n8.x4.trans.shared.b16 {%0,%1,%2,%3}, [%4];"
                 : "=r"(r[0]), "=r"(r[1]), "=r"(r[2]), "=r"(r[3]) : "r"(addr));
}
__device__ __forceinline__ void mma_f16(float* d, const uint32_t* a, uint32_t b0, uint32_t b1) {
    asm volatile(
        "mma.sync.aligned.m16n8k16.row.col.f32.f16.f16.f32 "
        "{%0,%1,%2,%3}, {%4,%5,%6,%7}, {%8,%9}, {%0,%1,%2,%3};"
        : "+f"(d[0]), "+f"(d[1]), "+f"(d[2]), "+f"(d[3])
        : "r"(a[0]), "r"(a[1]), "r"(a[2]), "r"(a[3]), "r"(b0), "r"(b1));
}
__device__ __forceinline__ uint32_t h2u(__half2 h) { return *(uint32_t*)&h; }

__global__ void __launch_bounds__(1024, 1)
block_diag_hmma(const float* __restrict__ x,
                const float* __restrict__ blocks,
                float* __restrict__ out) {
    extern __shared__ char smem[];
    const uint32_t sbase = smem_u32(smem);

    const int tid   = threadIdx.x;
    const int wid   = tid >> 5;
    const int lid   = tid & 31;
    const int bx    = blockIdx.x;
    const int dblk  = bx >> 2;
    const int chunk = bx & 3;
    const int k0    = dblk * 256;
    const int col0  = k0 + chunk * 64;

    // ================= stage phase =================
    // B first (unique DRAM bytes), then A. 4 f4 each per thread.
    {
        float4 vb[4], va[4];
        #pragma unroll
        for (int p = 0; p < 4; ++p) {
            int ib = p * 1024 + tid;
            int k  = ib >> 4;             // 0..255
            int sq = ib & 15;             // f4 along N
            vb[p] = *(const float4*)(blocks + (size_t)(k0 + k) * NROW + col0 + sq * 4);
        }
        #pragma unroll
        for (int p = 0; p < 4; ++p) {
            int ia = p * 1024 + tid;
            int m  = ia >> 6;             // 0..63
            int q  = ia & 63;             // f4 along K
            va[p] = *(const float4*)(x + (size_t)m * NROW + k0 + q * 4);
        }
        char* Ah = smem + OFF_AH;
        char* Bh = smem + OFF_BH;
        #pragma unroll
        for (int p = 0; p < 4; ++p) {
            int ib = p * 1024 + tid;
            int k  = ib >> 4;
            int sq = ib & 15;
            uint32_t offB = (uint32_t)(k * 128 + (((sq >> 1) ^ (k & 7)) * 16 + (sq & 1) * 8));
            __half2 b01 = __floats2half2_rn(vb[p].x, vb[p].y);
            __half2 b23 = __floats2half2_rn(vb[p].z, vb[p].w);
            *(uint32_t*)(Bh + offB)     = h2u(b01);
            *(uint32_t*)(Bh + offB + 4) = h2u(b23);
        }
        #pragma unroll
        for (int p = 0; p < 4; ++p) {
            int ia = p * 1024 + tid;
            int m  = ia >> 6;
            int q  = ia & 63;
            int g = q >> 1, hh = q & 1;
            uint32_t offA = (uint32_t)(m * 512 + ((g ^ (m & 7)) * 16 + hh * 8));
            __half2 a01 = __floats2half2_rn(va[p].x, va[p].y);
            __half2 a23 = __floats2half2_rn(va[p].z, va[p].w);
            *(uint32_t*)(Ah + offA)     = h2u(a01);
            *(uint32_t*)(Ah + offA + 4) = h2u(a23);
        }
    }

    __syncthreads();

    // ================= compute phase =================
    // half h: warps [h*16, h*16+16) cover k in [h*128, h*128+128), 8 ksteps.
    // within half: 4m x 4n grid of 16x16 warp tiles.
    const int h  = wid >> 4;
    const int wl = wid & 15;
    const int wm = wl & 3;
    const int wn = wl >> 2;
    const int m_base = wm * 16;
    const int n_base = wn * 16;

    const int a_row = m_base + (lid & 15);
    const int a_ch  = lid >> 4;
    const int a_rx  = a_row & 7;
    const uint32_t a_rowbase = sbase + OFF_AH + (uint32_t)(a_row * 512);

    const int b_g   = (wn * 2 + (lid >> 4)) ^ (lid & 7);
    const uint32_t b_base = sbase + OFF_BH
        + (uint32_t)(h * 16384 + (lid & 15) * 128 + b_g * 16);

    float acc[2][4] = {};
    uint32_t a[4], b[4];

    #pragma unroll
    for (int ks = 0; ks < 8; ++ks) {
        int G = (h * 8 + ks) * 2 + a_ch;          // global 16B granule along K
        uint32_t a_off = a_rowbase + (uint32_t)((G ^ a_rx) * 16);
        ldsm_x4(a, a_off);
        ldsm_x4_t(b, b_base + (uint32_t)(ks * 2048));
        mma_f16(acc[0], a, b[0], b[1]);
        mma_f16(acc[1], a, b[2], b[3]);
    }

    // ================= reduction + store =================
    __syncthreads();                       // all LDSM done; staging smem reusable
    float* red = (float*)smem;             // [16 warps][32 lanes][8 floats] = 16KB
    if (h == 1) {
        float4* dst = (float4*)(red + (wl * 32 + lid) * 8);
        dst[0] = make_float4(acc[0][0], acc[0][1], acc[0][2], acc[0][3]);
        dst[1] = make_float4(acc[1][0], acc[1][1], acc[1][2], acc[1][3]);
    }
    __syncthreads();
    if (h == 0) {
        const float4* src = (const float4*)(red + (wl * 32 + lid) * 8);
        float4 p0 = src[0];
        float4 p1 = src[1];
        const int grp = lid >> 2;
        const int tc  = lid & 3;
        const int row0 = m_base + grp;
        const int row1 = row0 + 8;
        {
            int col = col0 + n_base + tc * 2;
            *(float2*)(out + (size_t)row0 * NROW + col)
                = make_float2(acc[0][0] + p0.x, acc[0][1] + p0.y);
            *(float2*)(out + (size_t)row1 * NROW + col)
                = make_float2(acc[0][2] + p0.z, acc[0][3] + p0.w);
        }
        {
            int col = col0 + n_base + 8 + tc * 2;
            *(float2*)(out + (size_t)row0 * NROW + col)
                = make_float2(acc[1][0] + p1.x, acc[1][1] + p1.y);
            *(float2*)(out + (size_t)row1 * NROW + col)
                = make_float2(acc[1][2] + p1.z, acc[1][3] + p1.w);
        }
    }
}

extern "C" void kernel_launch(void* const* d_in, const int* in_sizes, int n_in,
                              void* d_out, int out_size) {
    const float* x      = (const float*)d_in[0];
    const float* blocks = (const float*)d_in[1];
    float* out = (float*)d_out;

    cudaFuncSetAttribute(block_diag_hmma,
                         cudaFuncAttributeMaxDynamicSharedMemorySize, SMEM_BYTES);
    block_diag_hmma<<<128, 1024, SMEM_BYTES>>>(x, blocks, out);
}